// round 3
// baseline (speedup 1.0000x reference)
#include <cuda_runtime.h>

// QCONVbk: quantum conv reduces analytically to
//   out[b,f,h,w] = sum_c prod_{k=1..8} cos( patch_k(b,c,h,w) + weights[0,k] )
// (wire-0 angle drops out; see Heisenberg-picture derivation: the CNOT ring maps
//  Z0 -> Z1 Z2 ... Z8, and for the RX product state <Zq> = cos(a_q + w_q)).

#define BB 8
#define CC 4
#define HH 32
#define WW 32
#define FF 8

__global__ void __launch_bounds__(256) qconv_kernel(
    const float* __restrict__ x,      // (B, C, H, W)
    const float* __restrict__ wts,    // (1, 9)
    float* __restrict__ out)          // (B, 8, H, W)
{
    int idx = blockIdx.x * blockDim.x + threadIdx.x;   // over B*H*W = 8192
    if (idx >= BB * HH * WW) return;
    int w = idx & (WW - 1);
    int h = (idx >> 5) & (HH - 1);
    int b = idx >> 10;

    // weights 1..8 (wire 0 irrelevant)
    float wk1 = __ldg(&wts[1]);
    float wk2 = __ldg(&wts[2]);
    float wk3 = __ldg(&wts[3]);
    float wk4 = __ldg(&wts[4]);
    float wk5 = __ldg(&wts[5]);
    float wk6 = __ldg(&wts[6]);
    float wk7 = __ldg(&wts[7]);
    float wk8 = __ldg(&wts[8]);
    const float wk[9] = {0.f, wk1, wk2, wk3, wk4, wk5, wk6, wk7, wk8};

    float sum = 0.0f;
    #pragma unroll
    for (int c = 0; c < CC; c++) {
        const float* xc = x + ((size_t)(b * CC + c)) * HH * WW;
        float prod = 1.0f;
        #pragma unroll
        for (int p = 0; p < 3; p++) {
            #pragma unroll
            for (int q = 0; q < 3; q++) {
                int k = p * 3 + q;
                if (k == 0) continue;               // wire 0 drops out
                int hh = h + p - 1;
                int ww = w + q - 1;
                float a = 0.0f;                     // zero padding -> angle 0
                if (hh >= 0 && hh < HH && ww >= 0 && ww < WW)
                    a = __ldg(&xc[hh * WW + ww]);
                prod *= cosf(a + wk[k]);
            }
        }
        sum += prod;
    }

    float* ob = out + ((size_t)b) * FF * HH * WW + h * WW + w;
    #pragma unroll
    for (int f = 0; f < FF; f++)
        ob[f * HH * WW] = sum;
}

extern "C" void kernel_launch(void* const* d_in, const int* in_sizes, int n_in,
                              void* d_out, int out_size) {
    const float* x   = (const float*)d_in[0];   // (8,4,32,32) = 32768 floats
    const float* wts = (const float*)d_in[1];   // (1,9) = 9 floats
    float* out = (float*)d_out;                 // (8,8,32,32) = 65536 floats
    (void)in_sizes; (void)n_in; (void)out_size;

    const int total = BB * HH * WW;             // 8192
    qconv_kernel<<<(total + 255) / 256, 256>>>(x, wts, out);
}

// round 6
// speedup vs baseline: 1.2593x; 1.2593x over previous
#include <cuda_runtime.h>

// QCONVbk closed form:
//   out[b,f,h,w] = sum_c prod_{k=1..8} cos( patch_k(b,c,h,w) + weights[0,k] )
// (CNOT ring maps Z0 -> Z1..Z8 in the Heisenberg picture; RX product state
//  gives <Zq> = cos(a_q + w_q); wire-0 angle drops out.)

#define BB 8
#define CC 4
#define HH 32
#define WW 32
#define FF 8

__global__ void __launch_bounds__(64) qconv_kernel(
    const float* __restrict__ x,      // (B, C, H, W)
    const float* __restrict__ wts,    // (1, 9)
    float* __restrict__ out)          // (B, 8, H, W)
{
    int idx = blockIdx.x * blockDim.x + threadIdx.x;   // over B*H*W = 8192
    int w = idx & (WW - 1);
    int h = (idx >> 5) & (HH - 1);
    int b = idx >> 10;

    // weights for wires 1..8 (wire 0 irrelevant)
    float wk1 = __ldg(&wts[1]);
    float wk2 = __ldg(&wts[2]);
    float wk3 = __ldg(&wts[3]);
    float wk4 = __ldg(&wts[4]);
    float wk5 = __ldg(&wts[5]);
    float wk6 = __ldg(&wts[6]);
    float wk7 = __ldg(&wts[7]);
    float wk8 = __ldg(&wts[8]);

    // in-bounds predicates for the 3x3 neighborhood (zero pad -> angle 0)
    bool hu = (h > 0), hd = (h < HH - 1);
    bool wl = (w > 0), wr = (w < WW - 1);

    float sum = 0.0f;
    #pragma unroll
    for (int c = 0; c < CC; c++) {
        const float* xc = x + ((size_t)(b * CC + c)) * HH * WW + h * WW + w;

        // taps k=1..8 at (p,q) offsets; k=0 is (-1,-1) and drops out.
        float a1 = hu        ? __ldg(xc - WW    ) : 0.0f;   // (-1, 0)
        float a2 = (hu && wr)? __ldg(xc - WW + 1) : 0.0f;   // (-1,+1)
        float a3 = wl        ? __ldg(xc - 1     ) : 0.0f;   // ( 0,-1)
        float a4 =             __ldg(xc         );          // ( 0, 0)
        float a5 = wr        ? __ldg(xc + 1     ) : 0.0f;   // ( 0,+1)
        float a6 = (hd && wl)? __ldg(xc + WW - 1) : 0.0f;   // (+1,-1)
        float a7 = hd        ? __ldg(xc + WW    ) : 0.0f;   // (+1, 0)
        float a8 = (hd && wr)? __ldg(xc + WW + 1) : 0.0f;   // (+1,+1)

        float c1 = __cosf(a1 + wk1);
        float c2 = __cosf(a2 + wk2);
        float c3 = __cosf(a3 + wk3);
        float c4 = __cosf(a4 + wk4);
        float c5 = __cosf(a5 + wk5);
        float c6 = __cosf(a6 + wk6);
        float c7 = __cosf(a7 + wk7);
        float c8 = __cosf(a8 + wk8);

        // pairwise product tree (depth 3 instead of 7)
        float p01 = c1 * c2;
        float p23 = c3 * c4;
        float p45 = c5 * c6;
        float p67 = c7 * c8;
        float p0123 = p01 * p23;
        float p4567 = p45 * p67;
        sum += p0123 * p4567;
    }

    float* ob = out + ((size_t)b) * FF * HH * WW + h * WW + w;
    #pragma unroll
    for (int f = 0; f < FF; f++)
        ob[f * HH * WW] = sum;
}

extern "C" void kernel_launch(void* const* d_in, const int* in_sizes, int n_in,
                              void* d_out, int out_size) {
    const float* x   = (const float*)d_in[0];   // (8,4,32,32)
    const float* wts = (const float*)d_in[1];   // (1,9)
    float* out = (float*)d_out;                 // (8,8,32,32)
    (void)in_sizes; (void)n_in; (void)out_size;

    const int total = BB * HH * WW;             // 8192
    qconv_kernel<<<total / 64, 64>>>(x, wts, out);
}